// round 5
// baseline (speedup 1.0000x reference)
#include <cuda_runtime.h>
#include <cuda_bf16.h>

// CoPEWithFIRE fused: B=1, H=12, S=768, W=32
// Row split across 2 warps (384 elems each) to halve per-warp state and
// raise occupancy. PWL eval in pos domain; log2-based with ln2 folded into
// per-segment slope.

#define CPF_S   768
#define CPF_W   32
#define CPF_H   12
#define CPF_HC  3        // chunks (of 128) per half-row
#define CPF_RPB 4        // rows per 256-thread block (2 warps per row)
#define LN2F    0.69314718056f

__global__ __launch_bounds__(256, 6)
void cope_fire_fused(const float* __restrict__ logits,
                     const float* __restrict__ W_in,
                     const float* __restrict__ b_in,
                     const float* __restrict__ W_out,
                     const float* __restrict__ b_out,
                     const float* __restrict__ c_ptr,
                     const float* __restrict__ lm_ptr,
                     const float* __restrict__ il_ptr,
                     float* __restrict__ out)
{
    __shared__ float  s_bp[CPF_W];          // sorted breakpoints (dist dom)
    __shared__ float  s_sl[CPF_W + 1];
    __shared__ float  s_ic[CPF_W + 1];
    __shared__ float  s_tmp[CPF_W];
    __shared__ float  s_half[8];                  // per-warp half totals
    __shared__ float  s_pbp[CPF_RPB][CPF_W];      // pos-domain bps per row
    __shared__ float2 s_seg[CPF_RPB][CPF_W + 1];  // (slope*ln2/denom, icept)

    const int tid  = threadIdx.x;
    const int lane = tid & 31;
    const int wid  = tid >> 5;
    const int pair = wid >> 1;        // row slot in block (0..3)
    const int half = wid & 1;         // 0 = first 384 elems, 1 = last 384

    const int row = blockIdx.x * CPF_RPB + pair;   // 768%4==0: block shares h
    const int h   = row / CPF_S;

    const float cabs = fabsf(*c_ptr);

    // ---------------- warp 0: build PWL tables for head h ----------------
    if (wid == 0) {
        const int w = lane;
        float w1 = W_in[w];
        float bi = b_in[w];
        float wo = W_out[h * CPF_W + w];
        bool  zero = (w1 == 0.0f);
        float bp  = zero ? 3.0e38f : (-bi / w1);
        float dsl = zero ? 0.0f : wo * fabsf(w1);
        float dic = zero ? 0.0f : ((w1 > 0.0f) ? wo * bi : -wo * bi);
        float bsl = (!zero && w1 < 0.0f) ? wo * w1 : 0.0f;
        float bic = zero ? wo * fmaxf(bi, 0.0f)
                         : ((w1 < 0.0f) ? wo * bi : 0.0f);
        #pragma unroll
        for (int off = 16; off >= 1; off >>= 1) {
            bsl += __shfl_xor_sync(0xFFFFFFFFu, bsl, off);
            bic += __shfl_xor_sync(0xFFFFFFFFu, bic, off);
        }
        bic += b_out[h];

        s_tmp[w] = bp;
        __syncwarp();
        int rank = 0;
        #pragma unroll
        for (int q = 0; q < CPF_W; ++q) {
            float o = s_tmp[q];
            rank += (o < bp || (o == bp && q < w)) ? 1 : 0;
        }
        __syncwarp();
        s_bp[rank]  = bp;
        s_tmp[rank] = dsl;
        __syncwarp();
        float v = s_tmp[lane];
        #pragma unroll
        for (int off = 1; off < 32; off <<= 1) {
            float t = __shfl_up_sync(0xFFFFFFFFu, v, off);
            if (lane >= off) v += t;
        }
        s_sl[lane + 1] = bsl + v;
        if (lane == 0) s_sl[0] = bsl;
        __syncwarp();
        s_tmp[rank] = dic;
        __syncwarp();
        float u = s_tmp[lane];
        #pragma unroll
        for (int off = 1; off < 32; off <<= 1) {
            float t = __shfl_up_sync(0xFFFFFFFFu, u, off);
            if (lane >= off) u += t;
        }
        s_ic[lane + 1] = bic + u;
        if (lane == 0) s_ic[0] = bic;
    }

    // -------- each warp: its half-row: load + sigmoid + scan --------------
    const long long base = (long long)row * CPF_S + half * (CPF_HC * 128);
    const float4* inp = (const float4*)(logits + base);
    float4*       op  = (float4*)(out + base);

    float g[CPF_HC][4];
    #pragma unroll
    for (int k = 0; k < CPF_HC; ++k) {
        float4 v4 = inp[k * 32 + lane];
        g[k][0] = 1.0f / (1.0f + __expf(-v4.x));
        g[k][1] = 1.0f / (1.0f + __expf(-v4.y));
        g[k][2] = 1.0f / (1.0f + __expf(-v4.z));
        g[k][3] = 1.0f / (1.0f + __expf(-v4.w));
    }

    #pragma unroll
    for (int k = 0; k < CPF_HC; ++k) {
        g[k][2] += g[k][3];
        g[k][1] += g[k][2];
        g[k][0] += g[k][1];
    }

    float Ctot[CPF_HC], after[CPF_HC];
    #pragma unroll
    for (int k = 0; k < CPF_HC; ++k) {
        float cs = g[k][0];
        float v = cs;
        #pragma unroll
        for (int off = 1; off < 32; off <<= 1) {
            float t = __shfl_down_sync(0xFFFFFFFFu, v, off);
            if (lane + off < 32) v += t;
        }
        after[k] = v - cs;
        Ctot[k]  = __shfl_sync(0xFFFFFFFFu, v, 0);
    }
    const float half_tot = Ctot[0] + Ctot[1] + Ctot[2];
    if (lane == 0) s_half[wid] = half_tot;

    __syncthreads();   // half totals + PWL tables ready

    const float partner_tot = s_half[wid ^ 1];
    const float row_total   = half_tot + partner_tot;

    // fold all suffix offsets into g: second half ends the row (tail 0),
    // first half sees everything in the second half after it.
    float acc = half ? 0.0f : partner_tot;
    #pragma unroll
    for (int k = CPF_HC - 1; k >= 0; --k) {
        float add = after[k] + acc;
        g[k][0] += add; g[k][1] += add; g[k][2] += add; g[k][3] += add;
        acc += Ctot[k];
    }

    // ------ per-row tables: pos-domain bps + (ln2/denom)-folded slopes ----
    const float thr   = fabsf((*lm_ptr) * (*il_ptr));
    const float denom = __logf(fmaf(cabs, fminf(row_total, thr), 1.0f)) + 1e-6f;
    const float scale = LN2F / denom;     // dist = log2(u) * scale
    const float rcp_c = 1.0f / cabs;

    // both warps of the pair write identical values: benign
    s_pbp[pair][lane] = (__expf(s_bp[lane] * denom) - 1.0f) * rcp_c;
    s_seg[pair][lane] = make_float2(s_sl[lane] * scale, s_ic[lane]);
    if (lane == 0)
        s_seg[pair][CPF_W] = make_float2(s_sl[CPF_W] * scale, s_ic[CPF_W]);
    __syncwarp();

    const float*  pbp  = s_pbp[pair];
    const float2* segt = s_seg[pair];

    const float r15 = pbp[15];
    const float r7  = pbp[7];
    const float r23 = pbp[23];

    // ---------------- eval: log2 || search, then one fma ------------------
    #pragma unroll
    for (int k = 0; k < CPF_HC; ++k) {
        float4 r;
        float* rp = &r.x;
        #pragma unroll
        for (int m = 0; m < 4; ++m) {
            const float pos = g[k][m];
            const float t = __log2f(fmaf(cabs, pos, 1.0f));  // MUFU chain
            int   seg = (pos >= r15) ? 16 : 0;               // reg levels
            float b2  = (pos >= r15) ? r23 : r7;
            seg += (pos >= b2) ? 8 : 0;
            #pragma unroll
            for (int st = 4; st >= 1; st >>= 1) {            // LDS levels
                int cand = seg + st;
                seg = (pos >= pbp[cand - 1]) ? cand : seg;
            }
            float2 si = segt[seg];
            rp[m] = fmaf(t, si.x, si.y);
        }
        op[k * 32 + lane] = r;
    }
}

extern "C" void kernel_launch(void* const* d_in, const int* in_sizes, int n_in,
                              void* d_out, int out_size)
{
    const float* logits = (const float*)d_in[0];  // (1,12,768,768)
    const float* W_in   = (const float*)d_in[1];  // (32,1)
    const float* b_in   = (const float*)d_in[2];  // (32,)
    const float* W_out  = (const float*)d_in[3];  // (12,32)
    const float* b_out  = (const float*)d_in[4];  // (12,)
    const float* c      = (const float*)d_in[5];
    const float* lmul   = (const float*)d_in[6];
    const float* initL  = (const float*)d_in[7];
    float* out = (float*)d_out;

    cope_fire_fused<<<(CPF_H * CPF_S) / CPF_RPB, 256>>>(
        logits, W_in, b_in, W_out, b_out, c, lmul, initL, out);
}